// round 15
// baseline (speedup 1.0000x reference)
#include <cuda_runtime.h>
#include <math.h>

#define BB 64
#define LL 128
#define HID 768
#define CDIM 256
#define SDIM 64
#define NOUT (CDIM + SDIM)      // 320
#define FEAT 321
#define NIT 30
#define EPSV 0.05f
#define L2E 1.4426950408889634f
#define INFN 3.0e38f
#define STH 256

__device__ __forceinline__ float ex2a(float x) {
    float y; asm("ex2.approx.f32 %0, %1;" : "=f"(y) : "f"(x)); return y;
}
__device__ __forceinline__ float lg2a(float x) {
    float y; asm("lg2.approx.f32 %0, %1;" : "=f"(y) : "f"(x)); return y;
}
// packed f32x2 add: returns a + b (lane-wise)
__device__ __forceinline__ float2 addx2(float2 a, float2 b) {
    float2 c;
    asm("{\n\t"
        ".reg .b64 ra, rb, rc;\n\t"
        "mov.b64 ra, {%2, %3};\n\t"
        "mov.b64 rb, {%4, %5};\n\t"
        "add.rn.f32x2 rc, ra, rb;\n\t"
        "mov.b64 {%0, %1}, rc;\n\t"
        "}"
        : "=f"(c.x), "=f"(c.y)
        : "f"(a.x), "f"(a.y), "f"(b.x), "f"(b.y));
    return c;
}

// ---------------- device scratch ---------------------------------------------
__device__ float g_Cs[BB * LL * LL];   // scaled cost (only [0,n)^2 valid)
__device__ float g_rep[BB * 2 * HID];
__device__ float g_fused[BB * NOUT];
__device__ float g_sink[3 * BB];
__device__ int   g_n0[BB], g_n1[BB];

// ---------------- K_prep: masked means + cls (local counts only) -------------
__global__ void __launch_bounds__(128) k_prep(
        const float* __restrict__ H, const int* __restrict__ tt,
        const int* __restrict__ am) {
    int b = blockIdx.x;
    int y = blockIdx.y;                    // 0..5
    int tid = threadIdx.x;                 // 128
    int d = y * 128 + tid;
    __shared__ float s_m0[LL], s_m1[LL];
    int a = am[b * LL + tid], t = tt[b * LL + tid];
    int f0 = (a == 1 && t == 0) ? 1 : 0;
    int f1 = (a == 1 && t == 1) ? 1 : 0;
    s_m0[tid] = (float)f0;
    s_m1[tid] = (float)f1;
    int n0 = __syncthreads_count(f0);
    int n1 = __syncthreads_count(f1);
    const float* Hb = H + (size_t)b * LL * HID;
    float a0 = 0.f, a1 = 0.f;
#pragma unroll 8
    for (int l = 0; l < LL; l++) {
        float h = Hb[l * HID + d];
        a0 += h * s_m0[l];
        a1 += h * s_m1[l];
    }
    float i0 = 1.f / fmaxf((float)n0, 1.f);
    float i1 = 1.f / fmaxf((float)n1, 1.f);
    g_rep[b * 2 * HID + d] = Hb[d];
    g_rep[b * 2 * HID + HID + d] = a0 * i0 - a1 * i1;
}

// ---------------- K_fused -----------------------------------------------------
#define FB 4
__global__ void __launch_bounds__(256) k_fused(
        const float* __restrict__ Wc, const float* __restrict__ bc,
        const float* __restrict__ Ws, const float* __restrict__ bs,
        const float* __restrict__ gate) {
    int b0 = blockIdx.y * FB;
    int w = threadIdx.x >> 5, lane = threadIdx.x & 31;
    int o = blockIdx.x * 8 + w;
    __shared__ __align__(16) float s_rep[FB][2 * HID];
    {
        const float4* g4 = (const float4*)(g_rep + (size_t)b0 * 2 * HID);
        float4* s4 = (float4*)&s_rep[0][0];
        for (int i = threadIdx.x; i < FB * (2 * HID) / 4; i += 256) s4[i] = g4[i];
    }
    __syncthreads();
    const float* W = (o < CDIM) ? (Wc + (size_t)o * 2 * HID)
                                : (Ws + (size_t)(o - CDIM) * 2 * HID);
    const float4* W4 = (const float4*)W;
    float acc[FB] = {};
#pragma unroll
    for (int t = 0; t < 12; t++) {
        float4 wv = W4[lane + 32 * t];
#pragma unroll
        for (int bb = 0; bb < FB; bb++) {
            float4 rv = *(const float4*)&s_rep[bb][4 * (lane + 32 * t)];
            acc[bb] += wv.x * rv.x + wv.y * rv.y + wv.z * rv.z + wv.w * rv.w;
        }
    }
#pragma unroll
    for (int off = 16; off; off >>= 1)
#pragma unroll
        for (int bb = 0; bb < FB; bb++)
            acc[bb] += __shfl_down_sync(0xffffffffu, acc[bb], off);
    if (lane == 0) {
        float gv = 1.f / (1.f + expf(-gate[0]));
        float bias = (o < CDIM) ? bc[o] : bs[o - CDIM];
        float sc = (o < CDIM) ? (1.f - gv) : gv;
#pragma unroll
        for (int bb = 0; bb < FB; bb++)
            g_fused[(b0 + bb) * NOUT + o] = (acc[bb] + bias) * sc;
    }
}

// ---------------- K_gram: self-contained (n0/n1, own sq) ----------------------
#define BT 64
#define BK 32
__global__ void __launch_bounds__(256) k_gram(const float* __restrict__ H,
                                              const int* __restrict__ am,
                                              const int* __restrict__ tt) {
    const int TI[3] = {0, 0, 1};
    const int TJ[3] = {0, 1, 1};
    int b = blockIdx.y;
    int t = blockIdx.x;
    int ti = TI[t], tj = TJ[t];
    int i0 = ti * BT, j0 = tj * BT;
    int tid = threadIdx.x;            // 256
    int av = (tid < LL) ? am[b * LL + tid] : 0;
    int tv = (tid < LL) ? tt[b * LL + tid] : 1;
    int n  = __syncthreads_count(av == 1);
    int n0 = __syncthreads_count(av == 1 && tv == 0);
    if (t == 0 && tid == 0) { g_n0[b] = n0; g_n1[b] = n - n0; }
    if (i0 >= n || j0 >= n) return;
    __shared__ __align__(16) float sA[BK * (BT + 4)];
    __shared__ __align__(16) float sB[BK * (BT + 4)];
    __shared__ float s_sqA[BT], s_sqB[BT];
    int tx = tid & 15, ty = tid >> 4;
    float acc[4][4] = {};
    const float* Hb = H + (size_t)b * LL * HID;
    int lr = tid >> 3;
    int lc = tid & 7;
    float sqa0 = 0.f, sqa1 = 0.f, sqb0 = 0.f, sqb1 = 0.f;
    for (int k0 = 0; k0 < HID; k0 += BK) {
#pragma unroll
        for (int h = 0; h < 2; h++) {
            int row = lr + 32 * h;
            float4 v = *(const float4*)(Hb + (size_t)(i0 + row) * HID + k0 + lc * 4);
            sA[(lc * 4 + 0) * (BT + 4) + row] = v.x;
            sA[(lc * 4 + 1) * (BT + 4) + row] = v.y;
            sA[(lc * 4 + 2) * (BT + 4) + row] = v.z;
            sA[(lc * 4 + 3) * (BT + 4) + row] = v.w;
            float pa = v.x * v.x + v.y * v.y + v.z * v.z + v.w * v.w;
            if (h == 0) sqa0 += pa; else sqa1 += pa;
            float4 u = *(const float4*)(Hb + (size_t)(j0 + row) * HID + k0 + lc * 4);
            sB[(lc * 4 + 0) * (BT + 4) + row] = u.x;
            sB[(lc * 4 + 1) * (BT + 4) + row] = u.y;
            sB[(lc * 4 + 2) * (BT + 4) + row] = u.z;
            sB[(lc * 4 + 3) * (BT + 4) + row] = u.w;
            float pb = u.x * u.x + u.y * u.y + u.z * u.z + u.w * u.w;
            if (h == 0) sqb0 += pb; else sqb1 += pb;
        }
        __syncthreads();
#pragma unroll
        for (int kk = 0; kk < BK; kk++) {
            float4 av4 = *(const float4*)&sA[kk * (BT + 4) + ty * 4];
            float4 bv4 = *(const float4*)&sB[kk * (BT + 4) + tx * 4];
            float ar[4] = {av4.x, av4.y, av4.z, av4.w};
            float br[4] = {bv4.x, bv4.y, bv4.z, bv4.w};
#pragma unroll
            for (int r = 0; r < 4; r++)
#pragma unroll
                for (int c = 0; c < 4; c++) acc[r][c] += ar[r] * br[c];
        }
        __syncthreads();
    }
#pragma unroll
    for (int off = 4; off; off >>= 1) {
        sqa0 += __shfl_down_sync(0xffffffffu, sqa0, off, 8);
        sqa1 += __shfl_down_sync(0xffffffffu, sqa1, off, 8);
        sqb0 += __shfl_down_sync(0xffffffffu, sqb0, off, 8);
        sqb1 += __shfl_down_sync(0xffffffffu, sqb1, off, 8);
    }
    if (lc == 0) {
        s_sqA[lr] = sqa0; s_sqA[lr + 32] = sqa1;
        s_sqB[lr] = sqb0; s_sqB[lr + 32] = sqb1;
    }
    __syncthreads();
    float* out = g_Cs + (size_t)b * LL * LL;
#pragma unroll
    for (int r = 0; r < 4; r++) {
        int i = i0 + ty * 4 + r;
        float si = s_sqA[ty * 4 + r];
#pragma unroll
        for (int c = 0; c < 4; c++) {
            int j = j0 + tx * 4 + c;
            float d2 = si + s_sqB[tx * 4 + c] - 2.f * acc[r][c];
            float v = sqrtf(fmaxf(d2, 1e-6f)) * (L2E / EPSV);
            out[i * LL + j] = v;
            if (ti != tj) out[j * LL + i] = v;
        }
    }
}

// ---------------- K_sink helpers ---------------------------------------------
// loads NEGATED cost into registers (pad = -INF so exp -> 0)
template<int MAXB>
__device__ __forceinline__ void load_row_regs(float4* C, const float* base, int cstride,
                                              int width, int nblk, int slot0, bool active) {
#pragma unroll
    for (int bq = 0; bq < MAXB; bq++) {
        if (bq < nblk) {
#pragma unroll
            for (int q = 0; q < 2; q++) {
                int c0 = 4 * (slot0 + bq * 2 + q);
                float4 v;
                v.x = (active && c0 + 0 < width) ? -base[(c0 + 0) * cstride] : -INFN;
                v.y = (active && c0 + 1 < width) ? -base[(c0 + 1) * cstride] : -INFN;
                v.z = (active && c0 + 2 < width) ? -base[(c0 + 2) * cstride] : -INFN;
                v.w = (active && c0 + 3 < width) ? -base[(c0 + 3) * cstride] : -INFN;
                C[bq * 2 + q] = v;
            }
        }
    }
}

// LSE pass with previous-LSE stabilizer + exact max fallback; C holds -cost.
template<int MAXB, int SP>
__device__ __forceinline__ void reg_pass2(const float4* C, int nblk,
                                          const float4* __restrict__ u4slice,
                                          float* __restrict__ outv,
                                          float coef, int row, int part, bool active) {
    const unsigned wm = 0xffffffffu;
    if (__all_sync(wm, !active)) return;    // fully idle warp
    float m = coef - outv[row];
    float2 nm2; nm2.x = -m; nm2.y = -m;
    float s0 = 0.f, s1 = 0.f, s2 = 0.f, s3 = 0.f;
#pragma unroll
    for (int bq = 0; bq < MAXB; bq++) {
        if (bq < nblk) {
            float4 u0 = u4slice[bq * 2 + 0], c0 = C[bq * 2 + 0];
            float4 u1 = u4slice[bq * 2 + 1], c1 = C[bq * 2 + 1];
            float2 e0 = addx2(addx2(make_float2(u0.x, u0.y), make_float2(c0.x, c0.y)), nm2);
            float2 e1 = addx2(addx2(make_float2(u0.z, u0.w), make_float2(c0.z, c0.w)), nm2);
            float2 e2 = addx2(addx2(make_float2(u1.x, u1.y), make_float2(c1.x, c1.y)), nm2);
            float2 e3 = addx2(addx2(make_float2(u1.z, u1.w), make_float2(c1.z, c1.w)), nm2);
            s0 += ex2a(e0.x); s1 += ex2a(e0.y);
            s2 += ex2a(e1.x); s3 += ex2a(e1.y);
            s0 += ex2a(e2.x); s1 += ex2a(e2.y);
            s2 += ex2a(e3.x); s3 += ex2a(e3.y);
        }
    }
    float s = (s0 + s1) + (s2 + s3);
#pragma unroll
    for (int o = 1; o < SP; o <<= 1) s += __shfl_xor_sync(wm, s, o);
    bool bad = active && !(s > 1e-35f && s < 1e35f);
    if (__any_sync(wm, bad)) {
        // exact max-stabilized path (iter 0 and rare blow-ups); exponent = u + C
        float M0 = -INFN, M1 = -INFN;
#pragma unroll
        for (int bq = 0; bq < MAXB; bq++) {
            if (bq < nblk) {
                float4 u0 = u4slice[bq * 2 + 0], c0 = C[bq * 2 + 0];
                float4 u1 = u4slice[bq * 2 + 1], c1 = C[bq * 2 + 1];
                M0 = fmaxf(M0, fmaxf(u0.x + c0.x, u0.y + c0.y));
                M1 = fmaxf(M1, fmaxf(u0.z + c0.z, u0.w + c0.w));
                M0 = fmaxf(M0, fmaxf(u1.x + c1.x, u1.y + c1.y));
                M1 = fmaxf(M1, fmaxf(u1.z + c1.z, u1.w + c1.w));
            }
        }
        float mm = fmaxf(M0, M1);
#pragma unroll
        for (int o = 1; o < SP; o <<= 1) mm = fmaxf(mm, __shfl_xor_sync(wm, mm, o));
        float t0 = 0.f, t1 = 0.f, t2 = 0.f, t3 = 0.f;
#pragma unroll
        for (int bq = 0; bq < MAXB; bq++) {
            if (bq < nblk) {
                float4 u0 = u4slice[bq * 2 + 0], c0 = C[bq * 2 + 0];
                float4 u1 = u4slice[bq * 2 + 1], c1 = C[bq * 2 + 1];
                t0 += ex2a(u0.x + c0.x - mm); t1 += ex2a(u0.y + c0.y - mm);
                t2 += ex2a(u0.z + c0.z - mm); t3 += ex2a(u0.w + c0.w - mm);
                t0 += ex2a(u1.x + c1.x - mm); t1 += ex2a(u1.y + c1.y - mm);
                t2 += ex2a(u1.z + c1.z - mm); t3 += ex2a(u1.w + c1.w - mm);
            }
        }
        float ss = (t0 + t1) + (t2 + t3);
#pragma unroll
        for (int o = 1; o < SP; o <<= 1) ss += __shfl_xor_sync(wm, ss, o);
        if (bad) { m = mm; s = ss; }
    }
    if (active && part == 0) outv[row] = coef - (m + lg2a(s));
}

// ---------------- K_sink: 192 CTAs, register rows (no head) -------------------
__global__ void __launch_bounds__(STH) k_sink() {
    __shared__ __align__(16) float s_u[128], s_w[128];
    __shared__ float s_red[STH / 32];
    int bx = blockIdx.x;
    int vg = bx >> 6;                // 0,1,2 -> v 2,0,1 (largest first)
    int b = bx & 63;
    int v = (vg == 0) ? 2 : (vg == 1) ? 0 : 1;
    int n0 = g_n0[b], n1 = g_n1[b];
    int tid = threadIdx.x;
    const float* src = g_Cs + (size_t)b * LL * LL;
    const float4* u4 = (const float4*)s_u;
    const float4* w4 = (const float4*)s_w;

    int na, nb;
    if (v == 0) { na = n0; nb = n1; }
    else if (v == 1) { na = n0; nb = n0; }
    else { na = n1; nb = n1; }
    float la2 = -lg2a((float)na);
    float lb2 = -lg2a((float)nb);
    if (tid < 128) {
        s_u[tid] = (tid < nb) ? lb2 : 0.f;
        s_w[tid] = 0.f;
    }
    __syncthreads();

    if (v == 0) {
        int nb4 = (nb + 3) >> 2, na4 = (na + 3) >> 2;
        int nblkA = (nb4 + 7) >> 3;      // <= 4
        int nblkT = (na4 + 3) >> 2;      // <= 3
        int rowA = tid >> 2, partA = tid & 3;
        int rowT = tid >> 1, partT = tid & 1;
        bool actA = rowA < na, actT = rowT < nb;
        int rAc = actA ? rowA : 0, rTc = actT ? rowT : 0;
        float4 CA[8], CT[6];
        load_row_regs<4>(CA, src + rAc * LL + n0, 1, nb, nblkA, partA * nblkA * 2, actA);
        load_row_regs<3>(CT, src + n0 + rTc, LL, na, nblkT, partT * nblkT * 2, actT);
        for (int it = 0; it < NIT; it++) {
            reg_pass2<4, 4>(CA, nblkA, u4 + partA * nblkA * 2, s_w, la2, rowA, partA, actA);
            __syncthreads();
            reg_pass2<3, 2>(CT, nblkT, w4 + partT * nblkT * 2, s_u, lb2, rowT, partT, actT);
            __syncthreads();
        }
    } else if (v == 1) {
        int n4 = (na + 3) >> 2;
        int nblk = (n4 + 7) >> 3;        // <= 2
        int row = tid >> 2, part = tid & 3;
        bool act = row < na;
        int rc = act ? row : 0;
        float4 C[4];
        load_row_regs<2>(C, src + rc * LL, 1, na, nblk, part * nblk * 2, act);
        for (int it = 0; it < NIT; it++) {
            reg_pass2<2, 4>(C, nblk, u4 + part * nblk * 2, s_w, la2, row, part, act);
            __syncthreads();
            reg_pass2<2, 4>(C, nblk, w4 + part * nblk * 2, s_u, lb2, row, part, act);
            __syncthreads();
        }
    } else {
        int n4 = (na + 3) >> 2;
        int nblk = (n4 + 3) >> 2;        // <= 7
        int row = tid >> 1, part = tid & 1;
        bool act = row < na;
        int rc = act ? row : 0;
        float4 C[14];
        load_row_regs<7>(C, src + (n0 + rc) * LL + n0, 1, na, nblk, part * nblk * 2, act);
        for (int it = 0; it < NIT; it++) {
            reg_pass2<7, 2>(C, nblk, u4 + part * nblk * 2, s_w, la2, row, part, act);
            __syncthreads();
            reg_pass2<7, 2>(C, nblk, w4 + part * nblk * 2, s_u, lb2, row, part, act);
            __syncthreads();
        }
    }

    float val = 0.f;
    if (tid < na) val += (s_w[tid] - la2) * (1.f / (float)na);
    if (tid < nb) val += (s_u[tid] - lb2) * (1.f / (float)nb);
    val *= (EPSV / L2E);
#pragma unroll
    for (int o = 16; o; o >>= 1) val += __shfl_down_sync(0xffffffffu, val, o);
    int wid = tid >> 5;
    if ((tid & 31) == 0) s_red[wid] = val;
    __syncthreads();
    if (tid == 0) {
        float acc = 0.f;
#pragma unroll
        for (int i = 0; i < STH / 32; i++) acc += s_red[i];
        g_sink[v * BB + b] = acc;
    }
}

// ---------------- K_head: layernorm + classifier ------------------------------
__global__ void __launch_bounds__(128) k_head(
        const float* __restrict__ lnw, const float* __restrict__ lnb,
        const float* __restrict__ Wcls, const float* __restrict__ bcls,
        float* __restrict__ out) {
    int b = blockIdx.x, tid = threadIdx.x;  // 128
    __shared__ float s_feat[FEAT];
    __shared__ float s_r[8];
    float dot = g_sink[b] - 0.5f * (g_sink[BB + b] + g_sink[2 * BB + b]);
    for (int i = tid; i < FEAT; i += 128)
        s_feat[i] = (i < NOUT) ? g_fused[b * NOUT + i] : dot;
    __syncthreads();
    float s = 0.f, s2 = 0.f;
    for (int i = tid; i < FEAT; i += 128) {
        float x = s_feat[i];
        s += x; s2 += x * x;
    }
#pragma unroll
    for (int o = 16; o; o >>= 1) {
        s  += __shfl_down_sync(0xffffffffu, s, o);
        s2 += __shfl_down_sync(0xffffffffu, s2, o);
    }
    if ((tid & 31) == 0) { s_r[tid >> 5] = s; s_r[4 + (tid >> 5)] = s2; }
    __syncthreads();
    float S  = s_r[0] + s_r[1] + s_r[2] + s_r[3];
    float S2 = s_r[4] + s_r[5] + s_r[6] + s_r[7];
    float mu = S / (float)FEAT;
    float var = S2 / (float)FEAT - mu * mu;
    float rstd = rsqrtf(var + 1e-5f);
    float a0 = 0.f, a1 = 0.f;
    for (int i = tid; i < FEAT; i += 128) {
        float h = (s_feat[i] - mu) * rstd * lnw[i] + lnb[i];
        a0 += h * Wcls[i];
        a1 += h * Wcls[FEAT + i];
    }
#pragma unroll
    for (int o = 16; o; o >>= 1) {
        a0 += __shfl_down_sync(0xffffffffu, a0, o);
        a1 += __shfl_down_sync(0xffffffffu, a1, o);
    }
    __syncthreads();
    if ((tid & 31) == 0) { s_r[tid >> 5] = a0; s_r[4 + (tid >> 5)] = a1; }
    __syncthreads();
    if (tid == 0) {
        out[b * 2 + 0] = s_r[0] + s_r[1] + s_r[2] + s_r[3] + bcls[0];
        out[b * 2 + 1] = s_r[4] + s_r[5] + s_r[6] + s_r[7] + bcls[1];
    }
}

// ---------------- launch --------------------------------------------------------
extern "C" void kernel_launch(void* const* d_in, const int* in_sizes, int n_in,
                              void* d_out, int out_size) {
    const float* H    = (const float*)d_in[0];
    const int*   tt   = (const int*)d_in[1];
    const int*   am   = (const int*)d_in[2];
    const float* Wc   = (const float*)d_in[3];
    const float* bc   = (const float*)d_in[4];
    const float* Ws   = (const float*)d_in[5];
    const float* bs   = (const float*)d_in[6];
    const float* gate = (const float*)d_in[7];
    const float* lnw  = (const float*)d_in[8];
    const float* lnb  = (const float*)d_in[9];
    const float* Wcls = (const float*)d_in[10];
    const float* bcls = (const float*)d_in[11];
    float* out = (float*)d_out;

    static cudaStream_t s2 = nullptr;
    static cudaEvent_t ev0 = nullptr, ev1 = nullptr;
    if (s2 == nullptr) {
        cudaStreamCreateWithFlags(&s2, cudaStreamNonBlocking);
        cudaEventCreateWithFlags(&ev0, cudaEventDisableTiming);
        cudaEventCreateWithFlags(&ev1, cudaEventDisableTiming);
    }

    // fork: gram -> sink on s2 (sink does NOT depend on prep/fused)
    cudaEventRecord(ev0, 0);
    cudaStreamWaitEvent(s2, ev0, 0);
    k_gram<<<dim3(3, BB), 256, 0, s2>>>(H, am, tt);
    k_sink<<<3 * BB, STH, 0, s2>>>();
    cudaEventRecord(ev1, s2);

    // main stream: prep -> fused (hidden under gram+sink)
    k_prep<<<dim3(BB, 6), 128>>>(H, tt, am);
    k_fused<<<dim3(40, BB / FB), 256>>>(Wc, bc, Ws, bs, gate);

    // join, then head
    cudaStreamWaitEvent(0, ev1, 0);
    k_head<<<BB, 128>>>(lnw, lnb, Wcls, bcls, out);
}

// round 16
// speedup vs baseline: 1.0156x; 1.0156x over previous
#include <cuda_runtime.h>
#include <math.h>

#define BB 64
#define LL 128
#define HID 768
#define CDIM 256
#define SDIM 64
#define NOUT (CDIM + SDIM)      // 320
#define FEAT 321
#define NIT 30
#define EPSV 0.05f
#define L2E 1.4426950408889634f
#define INFN 3.0e38f
#define STH 256

__device__ __forceinline__ float ex2a(float x) {
    float y; asm("ex2.approx.f32 %0, %1;" : "=f"(y) : "f"(x)); return y;
}
__device__ __forceinline__ float lg2a(float x) {
    float y; asm("lg2.approx.f32 %0, %1;" : "=f"(y) : "f"(x)); return y;
}
// packed f32x2 add
__device__ __forceinline__ float2 addx2(float2 a, float2 b) {
    float2 c;
    asm("{\n\t"
        ".reg .b64 ra, rb, rc;\n\t"
        "mov.b64 ra, {%2, %3};\n\t"
        "mov.b64 rb, {%4, %5};\n\t"
        "add.rn.f32x2 rc, ra, rb;\n\t"
        "mov.b64 {%0, %1}, rc;\n\t"
        "}"
        : "=f"(c.x), "=f"(c.y)
        : "f"(a.x), "f"(a.y), "f"(b.x), "f"(b.y));
    return c;
}

// ---------------- device scratch ---------------------------------------------
__device__ float g_Cs[BB * LL * LL];   // scaled cost (only [0,n)^2 valid)
__device__ float g_rep[BB * 2 * HID];
__device__ float g_fused[BB * NOUT];
__device__ float g_sink[3 * BB];
__device__ int   g_n0[BB], g_n1[BB];

// ---------------- K_prep: masked means + cls ---------------------------------
__global__ void __launch_bounds__(128) k_prep(
        const float* __restrict__ H, const int* __restrict__ tt,
        const int* __restrict__ am) {
    int b = blockIdx.x;
    int y = blockIdx.y;                    // 0..5
    int tid = threadIdx.x;                 // 128
    int d = y * 128 + tid;
    __shared__ float s_m0[LL], s_m1[LL];
    int a = am[b * LL + tid], t = tt[b * LL + tid];
    int f0 = (a == 1 && t == 0) ? 1 : 0;
    int f1 = (a == 1 && t == 1) ? 1 : 0;
    s_m0[tid] = (float)f0;
    s_m1[tid] = (float)f1;
    int n0 = __syncthreads_count(f0);
    int n1 = __syncthreads_count(f1);
    const float* Hb = H + (size_t)b * LL * HID;
    float a0 = 0.f, a1 = 0.f;
#pragma unroll 8
    for (int l = 0; l < LL; l++) {
        float h = Hb[l * HID + d];
        a0 += h * s_m0[l];
        a1 += h * s_m1[l];
    }
    float i0 = 1.f / fmaxf((float)n0, 1.f);
    float i1 = 1.f / fmaxf((float)n1, 1.f);
    g_rep[b * 2 * HID + d] = Hb[d];
    g_rep[b * 2 * HID + HID + d] = a0 * i0 - a1 * i1;
}

// ---------------- K_fused -----------------------------------------------------
#define FB 4
__global__ void __launch_bounds__(256) k_fused(
        const float* __restrict__ Wc, const float* __restrict__ bc,
        const float* __restrict__ Ws, const float* __restrict__ bs,
        const float* __restrict__ gate) {
    int b0 = blockIdx.y * FB;
    int w = threadIdx.x >> 5, lane = threadIdx.x & 31;
    int o = blockIdx.x * 8 + w;
    __shared__ __align__(16) float s_rep[FB][2 * HID];
    {
        const float4* g4 = (const float4*)(g_rep + (size_t)b0 * 2 * HID);
        float4* s4 = (float4*)&s_rep[0][0];
        for (int i = threadIdx.x; i < FB * (2 * HID) / 4; i += 256) s4[i] = g4[i];
    }
    __syncthreads();
    const float* W = (o < CDIM) ? (Wc + (size_t)o * 2 * HID)
                                : (Ws + (size_t)(o - CDIM) * 2 * HID);
    const float4* W4 = (const float4*)W;
    float acc[FB] = {};
#pragma unroll
    for (int t = 0; t < 12; t++) {
        float4 wv = W4[lane + 32 * t];
#pragma unroll
        for (int bb = 0; bb < FB; bb++) {
            float4 rv = *(const float4*)&s_rep[bb][4 * (lane + 32 * t)];
            acc[bb] += wv.x * rv.x + wv.y * rv.y + wv.z * rv.z + wv.w * rv.w;
        }
    }
#pragma unroll
    for (int off = 16; off; off >>= 1)
#pragma unroll
        for (int bb = 0; bb < FB; bb++)
            acc[bb] += __shfl_down_sync(0xffffffffu, acc[bb], off);
    if (lane == 0) {
        float gv = 1.f / (1.f + expf(-gate[0]));
        float bias = (o < CDIM) ? bc[o] : bs[o - CDIM];
        float sc = (o < CDIM) ? (1.f - gv) : gv;
#pragma unroll
        for (int bb = 0; bb < FB; bb++)
            g_fused[(b0 + bb) * NOUT + o] = (acc[bb] + bias) * sc;
    }
}

// ---------------- K_gram: self-contained (n0/n1, own sq) ----------------------
#define BT 64
#define BK 32
__global__ void __launch_bounds__(256) k_gram(const float* __restrict__ H,
                                              const int* __restrict__ am,
                                              const int* __restrict__ tt) {
    const int TI[3] = {0, 0, 1};
    const int TJ[3] = {0, 1, 1};
    int b = blockIdx.y;
    int t = blockIdx.x;
    int ti = TI[t], tj = TJ[t];
    int i0 = ti * BT, j0 = tj * BT;
    int tid = threadIdx.x;            // 256
    int av = (tid < LL) ? am[b * LL + tid] : 0;
    int tv = (tid < LL) ? tt[b * LL + tid] : 1;
    int n  = __syncthreads_count(av == 1);
    int n0 = __syncthreads_count(av == 1 && tv == 0);
    if (t == 0 && tid == 0) { g_n0[b] = n0; g_n1[b] = n - n0; }
    if (i0 >= n || j0 >= n) return;
    __shared__ __align__(16) float sA[BK * (BT + 4)];
    __shared__ __align__(16) float sB[BK * (BT + 4)];
    __shared__ float s_sqA[BT], s_sqB[BT];
    int tx = tid & 15, ty = tid >> 4;
    float acc[4][4] = {};
    const float* Hb = H + (size_t)b * LL * HID;
    int lr = tid >> 3;
    int lc = tid & 7;
    float sqa0 = 0.f, sqa1 = 0.f, sqb0 = 0.f, sqb1 = 0.f;
    for (int k0 = 0; k0 < HID; k0 += BK) {
#pragma unroll
        for (int h = 0; h < 2; h++) {
            int row = lr + 32 * h;
            float4 v = *(const float4*)(Hb + (size_t)(i0 + row) * HID + k0 + lc * 4);
            sA[(lc * 4 + 0) * (BT + 4) + row] = v.x;
            sA[(lc * 4 + 1) * (BT + 4) + row] = v.y;
            sA[(lc * 4 + 2) * (BT + 4) + row] = v.z;
            sA[(lc * 4 + 3) * (BT + 4) + row] = v.w;
            float pa = v.x * v.x + v.y * v.y + v.z * v.z + v.w * v.w;
            if (h == 0) sqa0 += pa; else sqa1 += pa;
            float4 u = *(const float4*)(Hb + (size_t)(j0 + row) * HID + k0 + lc * 4);
            sB[(lc * 4 + 0) * (BT + 4) + row] = u.x;
            sB[(lc * 4 + 1) * (BT + 4) + row] = u.y;
            sB[(lc * 4 + 2) * (BT + 4) + row] = u.z;
            sB[(lc * 4 + 3) * (BT + 4) + row] = u.w;
            float pb = u.x * u.x + u.y * u.y + u.z * u.z + u.w * u.w;
            if (h == 0) sqb0 += pb; else sqb1 += pb;
        }
        __syncthreads();
#pragma unroll
        for (int kk = 0; kk < BK; kk++) {
            float4 av4 = *(const float4*)&sA[kk * (BT + 4) + ty * 4];
            float4 bv4 = *(const float4*)&sB[kk * (BT + 4) + tx * 4];
            float ar[4] = {av4.x, av4.y, av4.z, av4.w};
            float br[4] = {bv4.x, bv4.y, bv4.z, bv4.w};
#pragma unroll
            for (int r = 0; r < 4; r++)
#pragma unroll
                for (int c = 0; c < 4; c++) acc[r][c] += ar[r] * br[c];
        }
        __syncthreads();
    }
#pragma unroll
    for (int off = 4; off; off >>= 1) {
        sqa0 += __shfl_down_sync(0xffffffffu, sqa0, off, 8);
        sqa1 += __shfl_down_sync(0xffffffffu, sqa1, off, 8);
        sqb0 += __shfl_down_sync(0xffffffffu, sqb0, off, 8);
        sqb1 += __shfl_down_sync(0xffffffffu, sqb1, off, 8);
    }
    if (lc == 0) {
        s_sqA[lr] = sqa0; s_sqA[lr + 32] = sqa1;
        s_sqB[lr] = sqb0; s_sqB[lr + 32] = sqb1;
    }
    __syncthreads();
    float* out = g_Cs + (size_t)b * LL * LL;
#pragma unroll
    for (int r = 0; r < 4; r++) {
        int i = i0 + ty * 4 + r;
        float si = s_sqA[ty * 4 + r];
#pragma unroll
        for (int c = 0; c < 4; c++) {
            int j = j0 + tx * 4 + c;
            float d2 = si + s_sqB[tx * 4 + c] - 2.f * acc[r][c];
            float v = sqrtf(fmaxf(d2, 1e-6f)) * (L2E / EPSV);
            out[i * LL + j] = v;
            if (ti != tj) out[j * LL + i] = v;
        }
    }
}

// ---------------- K_sink helpers ---------------------------------------------
// loads NEGATED cost into registers (pad = -INF so exp -> 0)
template<int MAXB>
__device__ __forceinline__ void load_row_regs(float4* C, const float* base, int cstride,
                                              int width, int nblk, int slot0, bool active) {
#pragma unroll
    for (int bq = 0; bq < MAXB; bq++) {
        if (bq < nblk) {
#pragma unroll
            for (int q = 0; q < 2; q++) {
                int c0 = 4 * (slot0 + bq * 2 + q);
                float4 v;
                v.x = (active && c0 + 0 < width) ? -base[(c0 + 0) * cstride] : -INFN;
                v.y = (active && c0 + 1 < width) ? -base[(c0 + 1) * cstride] : -INFN;
                v.z = (active && c0 + 2 < width) ? -base[(c0 + 2) * cstride] : -INFN;
                v.w = (active && c0 + 3 < width) ? -base[(c0 + 3) * cstride] : -INFN;
                C[bq * 2 + q] = v;
            }
        }
    }
}

// LSE pass with previous-LSE stabilizer + exact max fallback; C holds -cost.
template<int MAXB, int SP>
__device__ __forceinline__ void reg_pass2(const float4* C, int nblk,
                                          const float4* __restrict__ u4slice,
                                          float* __restrict__ outv,
                                          float coef, int row, int part, bool active) {
    const unsigned wm = 0xffffffffu;
    if (__all_sync(wm, !active)) return;    // fully idle warp
    float m = coef - outv[row];
    float2 nm2; nm2.x = -m; nm2.y = -m;
    float s0 = 0.f, s1 = 0.f, s2 = 0.f, s3 = 0.f;
#pragma unroll
    for (int bq = 0; bq < MAXB; bq++) {
        if (bq < nblk) {
            float4 u0 = u4slice[bq * 2 + 0], c0 = C[bq * 2 + 0];
            float4 u1 = u4slice[bq * 2 + 1], c1 = C[bq * 2 + 1];
            float2 e0 = addx2(addx2(make_float2(u0.x, u0.y), make_float2(c0.x, c0.y)), nm2);
            float2 e1 = addx2(addx2(make_float2(u0.z, u0.w), make_float2(c0.z, c0.w)), nm2);
            float2 e2 = addx2(addx2(make_float2(u1.x, u1.y), make_float2(c1.x, c1.y)), nm2);
            float2 e3 = addx2(addx2(make_float2(u1.z, u1.w), make_float2(c1.z, c1.w)), nm2);
            s0 += ex2a(e0.x); s1 += ex2a(e0.y);
            s2 += ex2a(e1.x); s3 += ex2a(e1.y);
            s0 += ex2a(e2.x); s1 += ex2a(e2.y);
            s2 += ex2a(e3.x); s3 += ex2a(e3.y);
        }
    }
    float s = (s0 + s1) + (s2 + s3);
#pragma unroll
    for (int o = 1; o < SP; o <<= 1) s += __shfl_xor_sync(wm, s, o);
    bool bad = active && !(s > 1e-35f && s < 1e35f);
    if (__any_sync(wm, bad)) {
        float M0 = -INFN, M1 = -INFN;
#pragma unroll
        for (int bq = 0; bq < MAXB; bq++) {
            if (bq < nblk) {
                float4 u0 = u4slice[bq * 2 + 0], c0 = C[bq * 2 + 0];
                float4 u1 = u4slice[bq * 2 + 1], c1 = C[bq * 2 + 1];
                M0 = fmaxf(M0, fmaxf(u0.x + c0.x, u0.y + c0.y));
                M1 = fmaxf(M1, fmaxf(u0.z + c0.z, u0.w + c0.w));
                M0 = fmaxf(M0, fmaxf(u1.x + c1.x, u1.y + c1.y));
                M1 = fmaxf(M1, fmaxf(u1.z + c1.z, u1.w + c1.w));
            }
        }
        float mm = fmaxf(M0, M1);
#pragma unroll
        for (int o = 1; o < SP; o <<= 1) mm = fmaxf(mm, __shfl_xor_sync(wm, mm, o));
        float t0 = 0.f, t1 = 0.f, t2 = 0.f, t3 = 0.f;
#pragma unroll
        for (int bq = 0; bq < MAXB; bq++) {
            if (bq < nblk) {
                float4 u0 = u4slice[bq * 2 + 0], c0 = C[bq * 2 + 0];
                float4 u1 = u4slice[bq * 2 + 1], c1 = C[bq * 2 + 1];
                t0 += ex2a(u0.x + c0.x - mm); t1 += ex2a(u0.y + c0.y - mm);
                t2 += ex2a(u0.z + c0.z - mm); t3 += ex2a(u0.w + c0.w - mm);
                t0 += ex2a(u1.x + c1.x - mm); t1 += ex2a(u1.y + c1.y - mm);
                t2 += ex2a(u1.z + c1.z - mm); t3 += ex2a(u1.w + c1.w - mm);
            }
        }
        float ss = (t0 + t1) + (t2 + t3);
#pragma unroll
        for (int o = 1; o < SP; o <<= 1) ss += __shfl_xor_sync(wm, ss, o);
        if (bad) { m = mm; s = ss; }
    }
    if (active && part == 0) outv[row] = coef - (m + lg2a(s));
}

// ---------------- K_sink: 128 CTAs (v2 alone; v0 then v1 sequentially) --------
__global__ void __launch_bounds__(STH) k_sink() {
    __shared__ __align__(16) float s_u[128], s_w[128];
    __shared__ float s_red[STH / 32];
    int bx = blockIdx.x;
    int tid = threadIdx.x;
    int wid = tid >> 5;
    bool isV2 = bx < BB;
    int b = isV2 ? bx : bx - BB;
    int n0 = g_n0[b], n1 = g_n1[b];
    const float* src = g_Cs + (size_t)b * LL * LL;
    const float4* u4 = (const float4*)s_u;
    const float4* w4 = (const float4*)s_w;

    if (isV2) {
        // ---- v2: symmetric n1 x n1 at (n0, n0); SP=2 ----
        int na = n1;
        float la2 = -lg2a((float)na);
        if (tid < 128) {
            s_u[tid] = (tid < na) ? la2 : 0.f;
            s_w[tid] = 0.f;
        }
        __syncthreads();
        int n4 = (na + 3) >> 2;
        int nblk = (n4 + 3) >> 2;        // <= 7
        int row = tid >> 1, part = tid & 1;
        bool act = row < na;
        int rc = act ? row : 0;
        float4 C[14];
        load_row_regs<7>(C, src + (size_t)(n0 + rc) * LL + n0, 1, na, nblk, part * nblk * 2, act);
        for (int it = 0; it < NIT; it++) {
            reg_pass2<7, 2>(C, nblk, u4 + part * nblk * 2, s_w, la2, row, part, act);
            __syncthreads();
            reg_pass2<7, 2>(C, nblk, w4 + part * nblk * 2, s_u, la2, row, part, act);
            __syncthreads();
        }
        float val = 0.f;
        if (tid < na) val = ((s_w[tid] - la2) + (s_u[tid] - la2)) * (1.f / (float)na);
        val *= (EPSV / L2E);
#pragma unroll
        for (int o = 16; o; o >>= 1) val += __shfl_down_sync(0xffffffffu, val, o);
        if ((tid & 31) == 0) s_red[wid] = val;
        __syncthreads();
        if (tid == 0) {
            float acc = 0.f;
#pragma unroll
            for (int i = 0; i < STH / 32; i++) acc += s_red[i];
            g_sink[2 * BB + b] = acc;
        }
        return;
    }

    // ---- phase 1: v0 (n0 x n1 cross) ----
    {
        int na = n0, nb = n1;
        float la2 = -lg2a((float)na);
        float lb2 = -lg2a((float)nb);
        if (tid < 128) {
            s_u[tid] = (tid < nb) ? lb2 : 0.f;
            s_w[tid] = 0.f;
        }
        __syncthreads();
        int nb4 = (nb + 3) >> 2, na4 = (na + 3) >> 2;
        int nblkA = (nb4 + 7) >> 3;      // <= 4
        int nblkT = (na4 + 3) >> 2;      // <= 3
        int rowA = tid >> 2, partA = tid & 3;
        int rowT = tid >> 1, partT = tid & 1;
        bool actA = rowA < na, actT = rowT < nb;
        int rAc = actA ? rowA : 0, rTc = actT ? rowT : 0;
        float4 CA[8], CT[6];
        load_row_regs<4>(CA, src + rAc * LL + n0, 1, nb, nblkA, partA * nblkA * 2, actA);
        load_row_regs<3>(CT, src + n0 + rTc, LL, na, nblkT, partT * nblkT * 2, actT);
        for (int it = 0; it < NIT; it++) {
            reg_pass2<4, 4>(CA, nblkA, u4 + partA * nblkA * 2, s_w, la2, rowA, partA, actA);
            __syncthreads();
            reg_pass2<3, 2>(CT, nblkT, w4 + partT * nblkT * 2, s_u, lb2, rowT, partT, actT);
            __syncthreads();
        }
        float val = 0.f;
        if (tid < na) val += (s_w[tid] - la2) * (1.f / (float)na);
        if (tid < nb) val += (s_u[tid] - lb2) * (1.f / (float)nb);
        val *= (EPSV / L2E);
#pragma unroll
        for (int o = 16; o; o >>= 1) val += __shfl_down_sync(0xffffffffu, val, o);
        if ((tid & 31) == 0) s_red[wid] = val;
        __syncthreads();
        if (tid == 0) {
            float acc = 0.f;
#pragma unroll
            for (int i = 0; i < STH / 32; i++) acc += s_red[i];
            g_sink[0 * BB + b] = acc;
        }
        __syncthreads();
    }

    // ---- phase 2: v1 (symmetric n0 x n0) ----
    {
        int na = n0;
        float la2 = -lg2a((float)na);
        if (tid < 128) {
            s_u[tid] = (tid < na) ? la2 : 0.f;
            s_w[tid] = 0.f;
        }
        __syncthreads();
        int n4 = (na + 3) >> 2;
        int nblk = (n4 + 7) >> 3;        // <= 2
        int row = tid >> 2, part = tid & 3;
        bool act = row < na;
        int rc = act ? row : 0;
        float4 C[4];
        load_row_regs<2>(C, src + rc * LL, 1, na, nblk, part * nblk * 2, act);
        for (int it = 0; it < NIT; it++) {
            reg_pass2<2, 4>(C, nblk, u4 + part * nblk * 2, s_w, la2, row, part, act);
            __syncthreads();
            reg_pass2<2, 4>(C, nblk, w4 + part * nblk * 2, s_u, la2, row, part, act);
            __syncthreads();
        }
        float val = 0.f;
        if (tid < na) val = ((s_w[tid] - la2) + (s_u[tid] - la2)) * (1.f / (float)na);
        val *= (EPSV / L2E);
#pragma unroll
        for (int o = 16; o; o >>= 1) val += __shfl_down_sync(0xffffffffu, val, o);
        if ((tid & 31) == 0) s_red[wid] = val;
        __syncthreads();
        if (tid == 0) {
            float acc = 0.f;
#pragma unroll
            for (int i = 0; i < STH / 32; i++) acc += s_red[i];
            g_sink[1 * BB + b] = acc;
        }
    }
}

// ---------------- K_head: layernorm + classifier ------------------------------
__global__ void __launch_bounds__(128) k_head(
        const float* __restrict__ lnw, const float* __restrict__ lnb,
        const float* __restrict__ Wcls, const float* __restrict__ bcls,
        float* __restrict__ out) {
    int b = blockIdx.x, tid = threadIdx.x;  // 128
    __shared__ float s_feat[FEAT];
    __shared__ float s_r[8];
    float dot = g_sink[b] - 0.5f * (g_sink[BB + b] + g_sink[2 * BB + b]);
    for (int i = tid; i < FEAT; i += 128)
        s_feat[i] = (i < NOUT) ? g_fused[b * NOUT + i] : dot;
    __syncthreads();
    float s = 0.f, s2 = 0.f;
    for (int i = tid; i < FEAT; i += 128) {
        float x = s_feat[i];
        s += x; s2 += x * x;
    }
#pragma unroll
    for (int o = 16; o; o >>= 1) {
        s  += __shfl_down_sync(0xffffffffu, s, o);
        s2 += __shfl_down_sync(0xffffffffu, s2, o);
    }
    if ((tid & 31) == 0) { s_r[tid >> 5] = s; s_r[4 + (tid >> 5)] = s2; }
    __syncthreads();
    float S  = s_r[0] + s_r[1] + s_r[2] + s_r[3];
    float S2 = s_r[4] + s_r[5] + s_r[6] + s_r[7];
    float mu = S / (float)FEAT;
    float var = S2 / (float)FEAT - mu * mu;
    float rstd = rsqrtf(var + 1e-5f);
    float a0 = 0.f, a1 = 0.f;
    for (int i = tid; i < FEAT; i += 128) {
        float h = (s_feat[i] - mu) * rstd * lnw[i] + lnb[i];
        a0 += h * Wcls[i];
        a1 += h * Wcls[FEAT + i];
    }
#pragma unroll
    for (int o = 16; o; o >>= 1) {
        a0 += __shfl_down_sync(0xffffffffu, a0, o);
        a1 += __shfl_down_sync(0xffffffffu, a1, o);
    }
    __syncthreads();
    if ((tid & 31) == 0) { s_r[tid >> 5] = a0; s_r[4 + (tid >> 5)] = a1; }
    __syncthreads();
    if (tid == 0) {
        out[b * 2 + 0] = s_r[0] + s_r[1] + s_r[2] + s_r[3] + bcls[0];
        out[b * 2 + 1] = s_r[4] + s_r[5] + s_r[6] + s_r[7] + bcls[1];
    }
}

// ---------------- launch --------------------------------------------------------
extern "C" void kernel_launch(void* const* d_in, const int* in_sizes, int n_in,
                              void* d_out, int out_size) {
    const float* H    = (const float*)d_in[0];
    const int*   tt   = (const int*)d_in[1];
    const int*   am   = (const int*)d_in[2];
    const float* Wc   = (const float*)d_in[3];
    const float* bc   = (const float*)d_in[4];
    const float* Ws   = (const float*)d_in[5];
    const float* bs   = (const float*)d_in[6];
    const float* gate = (const float*)d_in[7];
    const float* lnw  = (const float*)d_in[8];
    const float* lnb  = (const float*)d_in[9];
    const float* Wcls = (const float*)d_in[10];
    const float* bcls = (const float*)d_in[11];
    float* out = (float*)d_out;

    static cudaStream_t s2 = nullptr;
    static cudaEvent_t ev0 = nullptr, ev1 = nullptr;
    if (s2 == nullptr) {
        cudaStreamCreateWithFlags(&s2, cudaStreamNonBlocking);
        cudaEventCreateWithFlags(&ev0, cudaEventDisableTiming);
        cudaEventCreateWithFlags(&ev1, cudaEventDisableTiming);
    }

    // fork: gram -> sink on s2 (sink does NOT depend on prep/fused)
    cudaEventRecord(ev0, 0);
    cudaStreamWaitEvent(s2, ev0, 0);
    k_gram<<<dim3(3, BB), 256, 0, s2>>>(H, am, tt);
    k_sink<<<2 * BB, STH, 0, s2>>>();
    cudaEventRecord(ev1, s2);

    // main stream: prep -> fused (hidden under gram+sink)
    k_prep<<<dim3(BB, 6), 128>>>(H, tt, am);
    k_fused<<<dim3(40, BB / FB), 256>>>(Wc, bc, Ws, bs, gate);

    // join, then head
    cudaStreamWaitEvent(0, ev1, 0);
    k_head<<<BB, 128>>>(lnw, lnb, Wcls, bcls, out);
}